// round 9
// baseline (speedup 1.0000x reference)
#include <cuda_runtime.h>
#include <math.h>

#define TT   1024
#define NA   512
#define MB   64
#define NM   32768                       // NA*MB elements per timestep slab
#define HALF ((size_t)NM * TT)           // elements per output tensor

typedef unsigned long long u64;

__device__ __forceinline__ u64 splat2(float v) {
    u64 r; asm("mov.b64 %0, {%1, %1};" : "=l"(r) : "f"(v)); return r;
}
__device__ __forceinline__ void fma2(u64& d, u64 a, u64 b) {
    asm("fma.rn.f32x2 %0, %1, %2, %3;" : "=l"(d) : "l"(a), "l"(b), "l"(d));
}
__device__ __forceinline__ void unpack2(u64 v, float& lo, float& hi) {
    asm("mov.b64 {%0, %1}, %2;" : "=f"(lo), "=f"(hi) : "l"(v));
}

// ---------------- scratch (device globals; allocation is forbidden) -------------
__device__ float g_X2[(size_t)TT * NM];          // [t][n][m] transposed x; reused for Y
__device__ float g_P [(size_t)TT * NM];          // [t][a][m] = Wax@x + ba
__device__ float g_A [((size_t)TT + 1) * NM];    // slot 0 = a0; slot t+1 = a_{t+1}
__device__ int   g_doneq[2][TT + 1][8];          // [mh][slot][octant]; 64 = complete

// ---------------- init: flags, seed a0 into slot 0 -------------------------------
__global__ void k_init(const float* __restrict__ a0) {
    if (blockIdx.x == 0) {
        int total = 2 * (TT + 1) * 8;
        int* f = &g_doneq[0][0][0];
        for (int i = threadIdx.x; i < total; i += blockDim.x) {
            int s = (i >> 3) % (TT + 1);
            f[i] = (s == 0) ? 64 : 0;
        }
    } else {
        int idx = (blockIdx.x - 1) * 256 + threadIdx.x;
        g_A[idx] = a0[idx];
    }
}

// ---------------- 32x32 tiled transpose -------------------------------------------
__device__ __forceinline__ void trans_body(const float* __restrict__ src,
                                           float* __restrict__ dst, int R, int C) {
    __shared__ float tile[32][33];
    int c0 = blockIdx.x * 32, r0 = blockIdx.y * 32;
    int tx = threadIdx.x, ty = threadIdx.y;
#pragma unroll
    for (int i = 0; i < 32; i += 8)
        tile[ty + i][tx] = src[(size_t)(r0 + ty + i) * C + (c0 + tx)];
    __syncthreads();
#pragma unroll
    for (int i = 0; i < 32; i += 8)
        dst[(size_t)(c0 + ty + i) * R + (r0 + tx)] = tile[tx][ty + i];
}
__global__ __launch_bounds__(256) void k_trans_x(const float* __restrict__ x) {
    trans_body(x, g_X2, NM, TT);          // [32768][1024] -> [1024][32768]
}
__global__ __launch_bounds__(256) void k_trans_a(float* __restrict__ out) {
    trans_body(g_A + NM, out, TT, NM);    // [1024][32768] -> [32768][1024]
}
__global__ __launch_bounds__(256) void k_trans_y(float* __restrict__ out) {
    trans_body(g_X2, out, TT, NM);
}

// ---------------- batched GEMM v2 (f32x2): C_t[128r x 64m] = W @ X_t (+bias) ------
// grid (4, 1024), 256 threads. Thread tile: 4 rows x 8 m (4 f32x2 pairs).
// W pre-splatted to u64 {w,w} in SMEM (stride 33 u64 -> N=1 on 4-row LDS.64).
template <bool SOFTMAX>
__device__ __forceinline__ void gemm_body(const float* __restrict__ W,
                                          const float* __restrict__ bias,
                                          const float* __restrict__ Xbase,
                                          float* __restrict__ Ybase) {
    __shared__ u64   Wsp[128 * 33];  // [row][k] pair-splatted, 33792 B
    __shared__ float Xs[32][64];     // [k][m] 8192 B

    int t   = blockIdx.y;
    int rb  = blockIdx.x;
    const float* X = Xbase + (size_t)t * NM;
    float*       Y = Ybase + (size_t)t * NM;
    int tid = threadIdx.x;
    int mq  = tid & 7;               // m0 = 8*mq
    int rq  = tid >> 3;              // r0 = 4*rq (32 groups)
    int r0  = rb * 128 + rq * 4;

    u64 acc[4][4];
#pragma unroll
    for (int i = 0; i < 4; i++)
#pragma unroll
        for (int j = 0; j < 4; j++) acc[i][j] = 0ull;

    for (int kt = 0; kt < 16; kt++) {
        __syncthreads();
        // stage W tile (128r x 32k): 1024 float4, 4/thread, splat to u64
#pragma unroll
        for (int p = 0; p < 4; p++) {
            int idx = tid + p * 256;
            int row = idx >> 3, c4 = idx & 7;
            float4 wv = *(const float4*)&W[(size_t)(rb * 128 + row) * NA +
                                           kt * 32 + c4 * 4];
            u64* d = &Wsp[row * 33 + c4 * 4];
            d[0] = splat2(wv.x); d[1] = splat2(wv.y);
            d[2] = splat2(wv.z); d[3] = splat2(wv.w);
        }
        // stage X tile (32k x 64m): 512 float4, 2/thread
#pragma unroll
        for (int p = 0; p < 2; p++) {
            int idx = tid + p * 256;
            int k = idx >> 4, m4 = idx & 15;
            *(float4*)&Xs[k][m4 * 4] =
                *(const float4*)&X[(size_t)(kt * 32 + k) * MB + m4 * 4];
        }
        __syncthreads();
#pragma unroll 8
        for (int k = 0; k < 32; k++) {
            ulonglong2 xa = *(ulonglong2*)&Xs[k][mq * 8];
            ulonglong2 xb = *(ulonglong2*)&Xs[k][mq * 8 + 4];
#pragma unroll
            for (int i = 0; i < 4; i++) {
                u64 wp = Wsp[(rq * 4 + i) * 33 + k];
                fma2(acc[i][0], wp, xa.x);
                fma2(acc[i][1], wp, xa.y);
                fma2(acc[i][2], wp, xb.x);
                fma2(acc[i][3], wp, xb.y);
            }
        }
    }

#pragma unroll
    for (int i = 0; i < 4; i++) {
        float v[8];
        unpack2(acc[i][0], v[0], v[1]);
        unpack2(acc[i][1], v[2], v[3]);
        unpack2(acc[i][2], v[4], v[5]);
        unpack2(acc[i][3], v[6], v[7]);
        float b = bias[r0 + i];
#pragma unroll
        for (int j = 0; j < 8; j++) v[j] += b;

        if (SOFTMAX) {
            // softmax over batch axis m: 8 local + 8 mq-lanes (xor < 8)
            float mx = v[0];
#pragma unroll
            for (int j = 1; j < 8; j++) mx = fmaxf(mx, v[j]);
#pragma unroll
            for (int o = 1; o < 8; o <<= 1)
                mx = fmaxf(mx, __shfl_xor_sync(0xffffffffu, mx, o));
            float s = 0.f;
#pragma unroll
            for (int j = 0; j < 8; j++) { v[j] = __expf(v[j] - mx); s += v[j]; }
#pragma unroll
            for (int o = 1; o < 8; o <<= 1)
                s += __shfl_xor_sync(0xffffffffu, s, o);
            float inv = 1.0f / s;
#pragma unroll
            for (int j = 0; j < 8; j++) v[j] *= inv;
        }
        *(float4*)&Y[(size_t)(r0 + i) * MB + mq * 8] =
            make_float4(v[0], v[1], v[2], v[3]);
        *(float4*)&Y[(size_t)(r0 + i) * MB + mq * 8 + 4] =
            make_float4(v[4], v[5], v[6], v[7]);
    }
}

__global__ __launch_bounds__(256) void k_gemmP(const float* __restrict__ Wax,
                                               const float* __restrict__ ba) {
    gemm_body<false>(Wax, ba, g_X2, g_P);
}
__global__ __launch_bounds__(256) void k_gemmY(const float* __restrict__ Wya,
                                               const float* __restrict__ by) {
    gemm_body<true>(Wya, by, g_A + NM, g_X2);
}

// ---------------- persistent recurrence v5: 128 CTAs x 256 thr --------------------
// warp w = k-octant; lane = m. ONE CTA bar per step: double-buffered partials,
// per-warp release (flag counts to 64 = 8 CTAs x 8 warps).
#define AST 33
#define SM_WAS (8 * 512)                  // 16 KB
#define SM_AS  (512 * AST)                // 67584 B
#define SM_PART (8 * 8 * 32)              // one partial buffer: 8 KB
#define RECUR_SMEM ((SM_WAS + SM_AS + 2 * SM_PART) * 4)

__global__ __launch_bounds__(256) void k_recur(const float* __restrict__ Waa) {
    extern __shared__ float sm[];
    float* Was   = sm;                    // [8 rows][512 k]
    float* As    = sm + SM_WAS;           // [512 k][33]
    float* partb = sm + SM_WAS + SM_AS;   // [2][8 ks][8 r][32 m]

    int bid = blockIdx.x;
    int rb  = bid >> 1;                   // 64 row blocks of 8
    int mh  = bid & 1;                    // m half
    int tid = threadIdx.x;
    int w   = tid >> 5;                   // warp = octant 0..7
    int l   = tid & 31;                   // lane = m

    // stage Waa rows once: 8 x 512 = 1024 float4, 4/thread
#pragma unroll
    for (int i = 0; i < 4; i++) {
        int f4  = tid + i * 256;
        int row = f4 >> 7, c4 = f4 & 127;
        float4 v = *(const float4*)&Waa[(size_t)(rb * 8 + row) * NA + c4 * 4];
        *(float4*)&Was[row * 512 + c4 * 4] = v;
    }
    __syncthreads();

    const size_t o  = (size_t)(rb * 8 + w) * MB + mh * 32 + l;   // my output elem
    const int*   fl = &g_doneq[mh][0][w];
    int oct_out = rb >> 3;                // octant my CTA's rows land in
    float* dst = As + w * 64 * AST;
    const float* ab = As + w * 64 * AST + l;
    const float* wb = Was + w * 64;

    for (int s = 0; s < TT; s++) {
        float* part = partb + (s & 1) * SM_PART;

        // prefetch P (independent of flags; hides L2 latency)
        float pv = g_P[(size_t)s * NM + o];

        // wait for octant w of slot s
        {
            int v;
            do {
                asm volatile("ld.acquire.gpu.global.u32 %0, [%1];"
                             : "=r"(v) : "l"(fl + (size_t)s * 8));
            } while (v < 64);
        }
        __syncwarp();

        // stage my octant: 64 k x 32 m = 512 float4, 16 per lane
        const float* src = g_A + (size_t)s * NM + (size_t)w * 64 * MB + mh * 32;
#pragma unroll
        for (int i = 0; i < 16; i++) {
            int idx = l + i * 32;
            int kq = idx >> 3, c4 = idx & 7;
            float4 a4 = *(const float4*)&src[(size_t)kq * MB + c4 * 4];
            float* d = &dst[kq * AST + c4 * 4];
            d[0] = a4.x; d[1] = a4.y; d[2] = a4.z; d[3] = a4.w;
        }
        __syncwarp();

        // compute: 8 rows x 64 k, m = lane
        float acc[8];
#pragma unroll
        for (int r = 0; r < 8; r++) acc[r] = 0.f;
#pragma unroll
        for (int u = 0; u < 64; u += 4) {
            float a0 = ab[(u + 0) * AST];
            float a1 = ab[(u + 1) * AST];
            float a2 = ab[(u + 2) * AST];
            float a3 = ab[(u + 3) * AST];
#pragma unroll
            for (int r = 0; r < 8; r++) {
                float4 wv = *(const float4*)&wb[r * 512 + u];   // warp-uniform
                acc[r] += wv.x * a0;
                acc[r] += wv.y * a1;
                acc[r] += wv.z * a2;
                acc[r] += wv.w * a3;
            }
        }
#pragma unroll
        for (int r = 0; r < 8; r++)
            part[(w * 8 + r) * 32 + l] = acc[r];
        __syncthreads();                   // the ONLY CTA bar per step

        // reduce over 8 octants: thread (w,l) owns (row w, m l)
        float z = pv;
#pragma unroll
        for (int ks = 0; ks < 8; ks++)
            z += part[(ks * 8 + w) * 32 + l];
        g_A[(size_t)(s + 1) * NM + o] = tanhf(z);

        // per-warp release: this warp's row is fully stored
        __syncwarp();
        if (l == 0)
            asm volatile("red.release.gpu.global.add.u32 [%0], %1;"
                         :: "l"(&g_doneq[mh][s + 1][oct_out]), "r"(1) : "memory");
    }
}

// ---------------- launch ----------------------------------------------------------
extern "C" void kernel_launch(void* const* d_in, const int* in_sizes, int n_in,
                              void* d_out, int out_size) {
    (void)in_sizes; (void)n_in; (void)out_size;
    const float* x   = (const float*)d_in[0];
    const float* a0  = (const float*)d_in[1];
    const float* Waa = (const float*)d_in[2];
    const float* Wax = (const float*)d_in[3];
    const float* Wya = (const float*)d_in[4];
    const float* ba  = (const float*)d_in[5];
    const float* by  = (const float*)d_in[6];
    float* out = (float*)d_out;

    cudaFuncSetAttribute(k_recur, cudaFuncAttributeMaxDynamicSharedMemorySize,
                         RECUR_SMEM);

    k_init<<<129, 256>>>(a0);
    k_trans_x<<<dim3(TT / 32, NM / 32), dim3(32, 8)>>>(x);     // x -> [t][n][m]
    k_gemmP<<<dim3(4, TT), 256>>>(Wax, ba);                    // P = Wax@X + ba
    k_recur<<<128, 256, RECUR_SMEM>>>(Waa);                    // a_t chain
    k_gemmY<<<dim3(4, TT), 256>>>(Wya, by);                    // Y = softmax(Wya@A+by)
    k_trans_a<<<dim3(NM / 32, TT / 32), dim3(32, 8)>>>(out);   // -> [n][m][t]
    k_trans_y<<<dim3(NM / 32, TT / 32), dim3(32, 8)>>>(out + HALF);
}

// round 10
// speedup vs baseline: 1.1400x; 1.1400x over previous
#include <cuda_runtime.h>
#include <math.h>

#define TT   1024
#define NA   512
#define MB   64
#define NM   32768                       // NA*MB elements per timestep slab
#define HALF ((size_t)NM * TT)           // elements per output tensor

// ---------------- scratch (device globals; allocation is forbidden) -------------
__device__ float g_X2[(size_t)TT * NM];          // [t][n][m] transposed x; reused for Y
__device__ float g_P [(size_t)TT * NM];          // [t][a][m] = Wax@x + ba
__device__ float g_A [((size_t)TT + 1) * NM];    // slot 0 = a0; slot t+1 = a_{t+1}
__device__ int   g_doneq[2][TT + 1][8];          // [mh][slot][octant]; 64 = complete

// ---------------- init: flags, seed a0 into slot 0 -------------------------------
__global__ void k_init(const float* __restrict__ a0) {
    if (blockIdx.x == 0) {
        int total = 2 * (TT + 1) * 8;
        int* f = &g_doneq[0][0][0];
        for (int i = threadIdx.x; i < total; i += blockDim.x) {
            int s = (i >> 3) % (TT + 1);
            f[i] = (s == 0) ? 64 : 0;
        }
    } else {
        int idx = (blockIdx.x - 1) * 256 + threadIdx.x;
        g_A[idx] = a0[idx];
    }
}

// ---------------- 32x32 tiled transpose -------------------------------------------
__device__ __forceinline__ void trans_body(const float* __restrict__ src,
                                           float* __restrict__ dst, int R, int C) {
    __shared__ float tile[32][33];
    int c0 = blockIdx.x * 32, r0 = blockIdx.y * 32;
    int tx = threadIdx.x, ty = threadIdx.y;
#pragma unroll
    for (int i = 0; i < 32; i += 8)
        tile[ty + i][tx] = src[(size_t)(r0 + ty + i) * C + (c0 + tx)];
    __syncthreads();
#pragma unroll
    for (int i = 0; i < 32; i += 8)
        dst[(size_t)(c0 + ty + i) * R + (r0 + tx)] = tile[tx][ty + i];
}
__global__ __launch_bounds__(256) void k_trans_x(const float* __restrict__ x) {
    trans_body(x, g_X2, NM, TT);          // [32768][1024] -> [1024][32768]
}
__global__ __launch_bounds__(256) void k_trans_a(float* __restrict__ out) {
    trans_body(g_A + NM, out, TT, NM);    // [1024][32768] -> [32768][1024]
}
__global__ __launch_bounds__(256) void k_trans_y(float* __restrict__ out) {
    trans_body(g_X2, out, TT, NM);
}

// ---------------- batched GEMM (scalar, known-good): C_t[64r x 64m] ---------------
template <bool SOFTMAX>
__device__ __forceinline__ void gemm_body(const float* __restrict__ W,
                                          const float* __restrict__ bias,
                                          const float* __restrict__ Xbase,
                                          float* __restrict__ Ybase) {
    __shared__ float Ws[64][32];
    __shared__ float Xs[32][64];

    int t   = blockIdx.y;
    int rb  = blockIdx.x;
    const float* X = Xbase + (size_t)t * NM;
    float*       Y = Ybase + (size_t)t * NM;
    int tid = threadIdx.x;
    int mq  = tid & 15;
    int rq  = tid >> 4;
    int r0  = rb * 64 + rq * 4;

    float acc[4][4];
#pragma unroll
    for (int i = 0; i < 4; i++)
#pragma unroll
        for (int j = 0; j < 4; j++) acc[i][j] = 0.f;

    for (int kt = 0; kt < 16; kt++) {
        __syncthreads();
        {
            int f4 = tid;
            int row = f4 >> 3, c4 = f4 & 7;
            *(float4*)&Ws[row][c4 * 4] =
                *(const float4*)&W[(size_t)(rb * 64 + row) * NA + kt * 32 + c4 * 4];
            f4 = tid + 256;
            row = f4 >> 3; c4 = f4 & 7;
            *(float4*)&Ws[row][c4 * 4] =
                *(const float4*)&W[(size_t)(rb * 64 + row) * NA + kt * 32 + c4 * 4];
        }
        {
            int f4 = tid;
            int k = f4 >> 4, m4 = f4 & 15;
            *(float4*)&Xs[k][m4 * 4] =
                *(const float4*)&X[(size_t)(kt * 32 + k) * MB + m4 * 4];
            f4 = tid + 256;
            k = f4 >> 4; m4 = f4 & 15;
            *(float4*)&Xs[k][m4 * 4] =
                *(const float4*)&X[(size_t)(kt * 32 + k) * MB + m4 * 4];
        }
        __syncthreads();
#pragma unroll 8
        for (int k = 0; k < 32; k++) {
            float4 xv = *(const float4*)&Xs[k][mq * 4];
#pragma unroll
            for (int i = 0; i < 4; i++) {
                float w = Ws[rq * 4 + i][k];
                acc[i][0] += w * xv.x;
                acc[i][1] += w * xv.y;
                acc[i][2] += w * xv.z;
                acc[i][3] += w * xv.w;
            }
        }
    }

    if (!SOFTMAX) {
#pragma unroll
        for (int i = 0; i < 4; i++) {
            float b = bias[r0 + i];
            float4 v = make_float4(acc[i][0] + b, acc[i][1] + b,
                                   acc[i][2] + b, acc[i][3] + b);
            *(float4*)&Y[(size_t)(r0 + i) * MB + mq * 4] = v;
        }
    } else {
#pragma unroll
        for (int i = 0; i < 4; i++) {
            float b  = bias[r0 + i];
            float v0 = acc[i][0] + b, v1 = acc[i][1] + b;
            float v2 = acc[i][2] + b, v3 = acc[i][3] + b;
            float mx = fmaxf(fmaxf(v0, v1), fmaxf(v2, v3));
#pragma unroll
            for (int o = 1; o < 16; o <<= 1)
                mx = fmaxf(mx, __shfl_xor_sync(0xffffffffu, mx, o));
            float e0 = __expf(v0 - mx), e1 = __expf(v1 - mx);
            float e2 = __expf(v2 - mx), e3 = __expf(v3 - mx);
            float s = e0 + e1 + e2 + e3;
#pragma unroll
            for (int o = 1; o < 16; o <<= 1)
                s += __shfl_xor_sync(0xffffffffu, s, o);
            float inv = 1.0f / s;
            *(float4*)&Y[(size_t)(r0 + i) * MB + mq * 4] =
                make_float4(e0 * inv, e1 * inv, e2 * inv, e3 * inv);
        }
    }
}

__global__ __launch_bounds__(256) void k_gemmP(const float* __restrict__ Wax,
                                               const float* __restrict__ ba) {
    gemm_body<false>(Wax, ba, g_X2, g_P);
}
__global__ __launch_bounds__(256) void k_gemmY(const float* __restrict__ Wya,
                                               const float* __restrict__ by) {
    gemm_body<true>(Wya, by, g_A + NM, g_X2);
}

// ---------------- persistent recurrence v5: 128 CTAs x 256 thr --------------------
// warp w = k-octant; lane = m. ONE CTA bar per step: double-buffered partials,
// per-warp release (flag counts to 64 = 8 CTAs x 8 warps).
#define AST 33
#define SM_WAS (8 * 512)                  // 16 KB
#define SM_AS  (512 * AST)                // 67584 B
#define SM_PART (8 * 8 * 32)              // one partial buffer: 8 KB
#define RECUR_SMEM ((SM_WAS + SM_AS + 2 * SM_PART) * 4)

__global__ __launch_bounds__(256) void k_recur(const float* __restrict__ Waa) {
    extern __shared__ float sm[];
    float* Was   = sm;                    // [8 rows][512 k]
    float* As    = sm + SM_WAS;           // [512 k][33]
    float* partb = sm + SM_WAS + SM_AS;   // [2][8 ks][8 r][32 m]

    int bid = blockIdx.x;
    int rb  = bid >> 1;                   // 64 row blocks of 8
    int mh  = bid & 1;                    // m half
    int tid = threadIdx.x;
    int w   = tid >> 5;                   // warp = octant 0..7
    int l   = tid & 31;                   // lane = m

    // stage Waa rows once: 8 x 512 = 1024 float4, 4/thread
#pragma unroll
    for (int i = 0; i < 4; i++) {
        int f4  = tid + i * 256;
        int row = f4 >> 7, c4 = f4 & 127;
        float4 v = *(const float4*)&Waa[(size_t)(rb * 8 + row) * NA + c4 * 4];
        *(float4*)&Was[row * 512 + c4 * 4] = v;
    }
    __syncthreads();

    const size_t o  = (size_t)(rb * 8 + w) * MB + mh * 32 + l;   // my output elem
    const int*   fl = &g_doneq[mh][0][w];
    int oct_out = rb >> 3;                // octant my CTA's rows land in
    float* dst = As + w * 64 * AST;
    const float* ab = As + w * 64 * AST + l;
    const float* wb = Was + w * 64;

    for (int s = 0; s < TT; s++) {
        float* part = partb + (s & 1) * SM_PART;

        // prefetch P (independent of flags; hides L2 latency)
        float pv = g_P[(size_t)s * NM + o];

        // wait for octant w of slot s
        {
            int v;
            do {
                asm volatile("ld.acquire.gpu.global.u32 %0, [%1];"
                             : "=r"(v) : "l"(fl + (size_t)s * 8));
            } while (v < 64);
        }
        __syncwarp();

        // stage my octant: 64 k x 32 m = 512 float4, 16 per lane
        const float* src = g_A + (size_t)s * NM + (size_t)w * 64 * MB + mh * 32;
#pragma unroll
        for (int i = 0; i < 16; i++) {
            int idx = l + i * 32;
            int kq = idx >> 3, c4 = idx & 7;
            float4 a4 = *(const float4*)&src[(size_t)kq * MB + c4 * 4];
            float* d = &dst[kq * AST + c4 * 4];
            d[0] = a4.x; d[1] = a4.y; d[2] = a4.z; d[3] = a4.w;
        }
        __syncwarp();

        // compute: 8 rows x 64 k, m = lane
        float acc[8];
#pragma unroll
        for (int r = 0; r < 8; r++) acc[r] = 0.f;
#pragma unroll
        for (int u = 0; u < 64; u += 4) {
            float a0 = ab[(u + 0) * AST];
            float a1 = ab[(u + 1) * AST];
            float a2 = ab[(u + 2) * AST];
            float a3 = ab[(u + 3) * AST];
#pragma unroll
            for (int r = 0; r < 8; r++) {
                float4 wv = *(const float4*)&wb[r * 512 + u];   // warp-uniform
                acc[r] += wv.x * a0;
                acc[r] += wv.y * a1;
                acc[r] += wv.z * a2;
                acc[r] += wv.w * a3;
            }
        }
#pragma unroll
        for (int r = 0; r < 8; r++)
            part[(w * 8 + r) * 32 + l] = acc[r];
        __syncthreads();                   // the ONLY CTA bar per step

        // reduce over 8 octants: thread (w,l) owns (row w, m l)
        float z = pv;
#pragma unroll
        for (int ks = 0; ks < 8; ks++)
            z += part[(ks * 8 + w) * 32 + l];
        g_A[(size_t)(s + 1) * NM + o] = tanhf(z);

        // per-warp release: this warp's row is fully stored
        __syncwarp();
        if (l == 0)
            asm volatile("red.release.gpu.global.add.u32 [%0], %1;"
                         :: "l"(&g_doneq[mh][s + 1][oct_out]), "r"(1) : "memory");
    }
}

// ---------------- launch ----------------------------------------------------------
extern "C" void kernel_launch(void* const* d_in, const int* in_sizes, int n_in,
                              void* d_out, int out_size) {
    (void)in_sizes; (void)n_in; (void)out_size;
    const float* x   = (const float*)d_in[0];
    const float* a0  = (const float*)d_in[1];
    const float* Waa = (const float*)d_in[2];
    const float* Wax = (const float*)d_in[3];
    const float* Wya = (const float*)d_in[4];
    const float* ba  = (const float*)d_in[5];
    const float* by  = (const float*)d_in[6];
    float* out = (float*)d_out;

    cudaFuncSetAttribute(k_recur, cudaFuncAttributeMaxDynamicSharedMemorySize,
                         RECUR_SMEM);

    k_init<<<129, 256>>>(a0);
    k_trans_x<<<dim3(TT / 32, NM / 32), dim3(32, 8)>>>(x);     // x -> [t][n][m]
    k_gemmP<<<dim3(8, TT), 256>>>(Wax, ba);                    // P = Wax@X + ba
    k_recur<<<128, 256, RECUR_SMEM>>>(Waa);                    // a_t chain
    k_gemmY<<<dim3(8, TT), 256>>>(Wya, by);                    // Y = softmax(Wya@A+by)
    k_trans_a<<<dim3(NM / 32, TT / 32), dim3(32, 8)>>>(out);   // -> [n][m][t]
    k_trans_y<<<dim3(NM / 32, TT / 32), dim3(32, 8)>>>(out + HALF);
}